// round 12
// baseline (speedup 1.0000x reference)
#include <cuda_runtime.h>
#include <cuda_bf16.h>
#include <cstdint>

#define NN 100000
#define EE 1600000
#define DD 64
#define GG 256
#define NPART 98   // ceil(NN/1024)

typedef unsigned long long ull;

// ---- scratch (no allocs allowed) ----
__device__ int   g_is32;
__device__ int   g_deg[NN];
__device__ int   g_off[NN + 1];
__device__ int   g_part[128];
__device__ int   g_cursor[NN];
__device__ int   g_csr[EE];
__device__ float g_agg[NN * DD];
__device__ float g_hA[NN * DD];
__device__ float g_hB[NN * DD];
// pre-swizzled bf16-split weights, row-major [k][n] 64x64, 128B rows:
// [3 layers * 2 mats]
__device__ unsigned short g_wbh[6][4096];
__device__ unsigned short g_wbl[6][4096];

// ---- packed f32x2 helper ----
__device__ __forceinline__ void add2(ull& d, ull b) {
    asm("add.rn.f32x2 %0, %0, %1;" : "+l"(d) : "l"(b));
}

__device__ __forceinline__ uint32_t sw128(uint32_t off) {
    return off ^ ((off >> 3) & 0x70);
}
__device__ __forceinline__ uint32_t s2u(const void* p) {
    return (uint32_t)__cvta_generic_to_shared(p);
}

// ---- warp-level tensor core ops (base sm_103 target: ldmatrix + mma.sync) ----
__device__ __forceinline__ void ldm4(uint32_t r[4], uint32_t addr) {
    asm volatile("ldmatrix.sync.aligned.m8n8.x4.shared.b16 {%0,%1,%2,%3}, [%4];"
                 : "=r"(r[0]), "=r"(r[1]), "=r"(r[2]), "=r"(r[3]) : "r"(addr));
}
__device__ __forceinline__ void ldm4t(uint32_t r[4], uint32_t addr) {
    asm volatile("ldmatrix.sync.aligned.m8n8.x4.trans.shared.b16 {%0,%1,%2,%3}, [%4];"
                 : "=r"(r[0]), "=r"(r[1]), "=r"(r[2]), "=r"(r[3]) : "r"(addr));
}
__device__ __forceinline__ void mma_bf16(float c[4], const uint32_t a[4],
                                         uint32_t b0, uint32_t b1) {
    asm volatile(
        "mma.sync.aligned.m16n8k16.row.col.f32.bf16.bf16.f32 "
        "{%0,%1,%2,%3}, {%4,%5,%6,%7}, {%8,%9}, {%0,%1,%2,%3};"
        : "+f"(c[0]), "+f"(c[1]), "+f"(c[2]), "+f"(c[3])
        : "r"(a[0]), "r"(a[1]), "r"(a[2]), "r"(a[3]), "r"(b0), "r"(b1));
}

// split helpers
__device__ __forceinline__ uint32_t bf2_hi(float x, float y) {
    __nv_bfloat162 h = __float22bfloat162_rn(make_float2(x, y));
    return *(uint32_t*)&h;
}
__device__ __forceinline__ uint32_t bf2_lo(float x, float y, uint32_t hi) {
    __nv_bfloat162 h = *(__nv_bfloat162*)&hi;
    __nv_bfloat162 l = __float22bfloat162_rn(
        make_float2(x - __low2float(h), y - __high2float(h)));
    return *(uint32_t*)&l;
}

// ---------------------------------------------------------------------------
__global__ __launch_bounds__(256) void zero_detect_kernel(const unsigned long long* __restrict__ ei) {
    int i = blockIdx.x * 256 + threadIdx.x;
    if (i < NN) g_deg[i] = 0;
    if (blockIdx.x == 0) {
        int bad = (ei[threadIdx.x] >> 32) != 0ull;
        int any = __syncthreads_or(bad);
        if (threadIdx.x == 0) g_is32 = any;
    }
}

__global__ __launch_bounds__(256) void hist_kernel(const void* __restrict__ ei) {
    int e = blockIdx.x * 256 + threadIdx.x;
    if (e >= EE) return;
    int d;
    if (g_is32) d = __ldg(&((const int*)ei)[EE + e]);
    else        d = (int)__ldg(&((const long long*)ei)[EE + e]);
    atomicAdd(&g_deg[d], 1);
}

__global__ __launch_bounds__(1024) void scan1_kernel() {
    __shared__ int warpTot[32];
    int tid = threadIdx.x, lane = tid & 31, warp = tid >> 5;
    int i = blockIdx.x * 1024 + tid;
    int v = (i < NN) ? g_deg[i] : 0;
    int x = v;
#pragma unroll
    for (int o = 1; o < 32; o <<= 1) {
        int t = __shfl_up_sync(0xffffffffu, x, o);
        if (lane >= o) x += t;
    }
    if (lane == 31) warpTot[warp] = x;
    __syncthreads();
    if (warp == 0) {
        int w = warpTot[lane];
        int y = w;
#pragma unroll
        for (int o = 1; o < 32; o <<= 1) {
            int t = __shfl_up_sync(0xffffffffu, y, o);
            if (lane >= o) y += t;
        }
        warpTot[lane] = y - w;
        if (lane == 31 && blockIdx.x < NPART) g_part[blockIdx.x] = y;
    }
    __syncthreads();
    if (i < NN) g_off[i] = x - v + warpTot[warp];
}

__global__ __launch_bounds__(256) void scan23_kernel() {
    __shared__ int p[128];
    int tid = threadIdx.x;
    if (tid < 128) p[tid] = (tid < NPART) ? g_part[tid] : 0;
    __syncthreads();
    int v = (tid < 128) ? p[tid] : 0;
#pragma unroll
    for (int d = 1; d < 128; d <<= 1) {
        int t = (tid < 128 && tid >= d) ? p[tid - d] : 0;
        __syncthreads();
        if (tid < 128) p[tid] += t;
        __syncthreads();
    }
    if (tid < 128) p[tid] -= v;
    __syncthreads();
    int i = blockIdx.x * 256 + tid;
    if (i < NN) {
        int o = g_off[i] + p[i >> 10];
        g_off[i] = o;
        g_cursor[i] = o;
    }
    if (i == 0) g_off[NN] = EE;
}

__global__ __launch_bounds__(256) void fill_kernel(const void* __restrict__ ei) {
    int e = blockIdx.x * 256 + threadIdx.x;
    if (e >= EE) return;
    int s, d;
    if (g_is32) {
        const int* p = (const int*)ei;
        s = __ldg(&p[e]); d = __ldg(&p[EE + e]);
    } else {
        const long long* p = (const long long*)ei;
        s = (int)__ldg(&p[e]); d = (int)__ldg(&p[EE + e]);
    }
    int pos = atomicAdd(&g_cursor[d], 1);
    g_csr[pos] = s;
}

// ---------------------------------------------------------------------------
// gather: z[d] = h[d] + sum_{s in csr[d]} h[s]. 16 threads/node, f32x2 adds.
// ---------------------------------------------------------------------------
__global__ __launch_bounds__(256) void gather_kernel(
    const ulonglong2* __restrict__ h, ulonglong2* __restrict__ z)
{
    int t = blockIdx.x * 256 + threadIdx.x;
    if (t >= NN * 16) return;
    int node = t >> 4, c = t & 15;
    ulonglong2 acc = h[node * 16 + c];
    int i = g_off[node], end = g_off[node + 1];
    int s_next = (i < end) ? __ldg(&g_csr[i]) : 0;
    while (i < end) {
        int s = s_next;
        i++;
        if (i < end) s_next = __ldg(&g_csr[i]);
        ulonglong2 v = h[s * 16 + c];
        add2(acc.x, v.x);
        add2(acc.y, v.y);
    }
    z[node * 16 + c] = acc;
}

// ---------------------------------------------------------------------------
// weight pre-convert: B mat = W row-major [k][n], bf16 hi+lo, SW128-pre-swizzled
// (128-byte rows) so kernel-side copies are linear and ldmatrix is conflict-free.
// ---------------------------------------------------------------------------
__global__ __launch_bounds__(256) void wconv_kernel(
    const float* w0, const float* w1, const float* w2,
    const float* w3, const float* w4, const float* w5)
{
    int i = blockIdx.x * 256 + threadIdx.x;    // 0..24575
    if (i >= 6 * 4096) return;
    int lm = i >> 12, r = i & 4095;
    const float* W = (lm == 0) ? w0 : (lm == 1) ? w1 : (lm == 2) ? w2
                   : (lm == 3) ? w3 : (lm == 4) ? w4 : w5;
    int k = r >> 6, n = r & 63;
    float v = W[r];
    __nv_bfloat16 hi = __float2bfloat16(v);
    __nv_bfloat16 lo = __float2bfloat16(v - __bfloat162float(hi));
    uint32_t off = sw128((uint32_t)(k * 128 + n * 2));
    g_wbh[lm][off >> 1] = *(unsigned short*)&hi;
    g_wbl[lm][off >> 1] = *(unsigned short*)&lo;
}

// ---------------------------------------------------------------------------
// tensor-core MLP via mma.sync bf16 split-GEMM (fp32 accuracy):
//   y = relu(z @ W1 + b1) @ W2 + b2
//   fcw == null : hout[node] = relu?(y)
//   fcw != null : out[batch[node]] += dot(y, fcw)
// 128 nodes/block, 256 threads = 8 warps; warp w owns rows [16w, 16w+16).
// ---------------------------------------------------------------------------
struct __align__(128) MSmem {
    char A_hi[16384];   // 128 rows x 128B (64 bf16), sw128
    char A_lo[16384];
    char B_hi[8192];    // 64 rows (k) x 128B (64 bf16), sw128
    char B_lo[8192];
};

// one split-GEMM stage: c[8][4] += A(128x64) @ B(64x64), 3-term bf16 split
__device__ __forceinline__ void mma_stage(uint32_t aHi, uint32_t aLo,
                                          uint32_t bHi, uint32_t bLo,
                                          int warp, int lane, float c[8][4])
{
#pragma unroll
    for (int i = 0; i < 8; i++)
#pragma unroll
        for (int j = 0; j < 4; j++) c[i][j] = 0.f;

    int mat = lane >> 3, r = lane & 7;
    // A lane address: m = warp*16 + (mat&1)*8 + r, k-bytes = kb*32 + (mat>>1)*16
    uint32_t aRow = (uint32_t)((warp * 16 + (mat & 1) * 8 + r) * 128 + (mat >> 1) * 16);
    // B lane address: k = kb*16 + (mat&1)*8 + r, n-bytes = np*32 + (mat>>1)*16
    uint32_t bRow = (uint32_t)(((mat & 1) * 8 + r) * 128 + (mat >> 1) * 16);

#pragma unroll
    for (int kb = 0; kb < 4; kb++) {
        uint32_t ah[4], al[4];
        uint32_t ao = sw128(aRow + kb * 32);
        ldm4(ah, aHi + ao);
        ldm4(al, aLo + ao);
#pragma unroll
        for (int np = 0; np < 4; np++) {
            uint32_t bh[4], bl[4];
            uint32_t bo = sw128(bRow + kb * 2048 + np * 32);
            ldm4t(bh, bHi + bo);
            ldm4t(bl, bLo + bo);
            int n0 = np * 2;
            mma_bf16(c[n0],     ah, bh[0], bh[1]);
            mma_bf16(c[n0 + 1], ah, bh[2], bh[3]);
            mma_bf16(c[n0],     ah, bl[0], bl[1]);
            mma_bf16(c[n0 + 1], ah, bl[2], bl[3]);
            mma_bf16(c[n0],     al, bh[0], bh[1]);
            mma_bf16(c[n0 + 1], al, bh[2], bh[3]);
        }
    }
}

__global__ __launch_bounds__(256) void mlp_mma_kernel(
    const float* __restrict__ z, int layer,
    const float* __restrict__ b1, const float* __restrict__ b2,
    float* __restrict__ hout, int relu_out,
    const float* __restrict__ fcw, const void* __restrict__ batch,
    float* __restrict__ out)
{
    __shared__ MSmem sm;
    int tid = threadIdx.x;
    int lane = tid & 31, warp = tid >> 5;
    int node0 = blockIdx.x * 128;

    uint32_t aHi = s2u(sm.A_hi), aLo = s2u(sm.A_lo);
    uint32_t bHi = s2u(sm.B_hi), bLo = s2u(sm.B_lo);

    // ---- load W1 tiles (pre-swizzled, linear copy) ----
    {
        const uint4* sh = (const uint4*)&g_wbh[layer * 2 + 0][0];
        const uint4* sl = (const uint4*)&g_wbl[layer * 2 + 0][0];
        ((uint4*)sm.B_hi)[tid] = sh[tid];
        ((uint4*)sm.B_hi)[tid + 256] = sh[tid + 256];
        ((uint4*)sm.B_lo)[tid] = sl[tid];
        ((uint4*)sm.B_lo)[tid + 256] = sl[tid + 256];
    }

    // ---- load z, split to bf16 hi/lo, store swizzled (thread = half row) ----
    {
        int row = tid >> 1, half = tid & 1;
        int node = node0 + row;
#pragma unroll
        for (int i = 0; i < 8; i++) {
            float4 v = make_float4(0.f, 0.f, 0.f, 0.f);
            if (node < NN) v = ((const float4*)z)[node * 16 + half * 8 + i];
            uint32_t h0 = bf2_hi(v.x, v.y), h1 = bf2_hi(v.z, v.w);
            uint32_t l0 = bf2_lo(v.x, v.y, h0), l1 = bf2_lo(v.z, v.w, h1);
            uint32_t o = sw128((uint32_t)(row * 128 + half * 64 + i * 8));
            *(ull*)(sm.A_hi + o) = ((ull)h1 << 32) | h0;
            *(ull*)(sm.A_lo + o) = ((ull)l1 << 32) | l0;
        }
    }
    __syncthreads();

    // ---- stage 1 ----
    float c[8][4];
    mma_stage(aHi, aLo, bHi, bLo, warp, lane, c);
    __syncthreads();   // all mma reads of A/B done

    // ---- load W2 tiles ----
    {
        const uint4* sh = (const uint4*)&g_wbh[layer * 2 + 1][0];
        const uint4* sl = (const uint4*)&g_wbl[layer * 2 + 1][0];
        ((uint4*)sm.B_hi)[tid] = sh[tid];
        ((uint4*)sm.B_hi)[tid + 256] = sh[tid + 256];
        ((uint4*)sm.B_lo)[tid] = sl[tid];
        ((uint4*)sm.B_lo)[tid + 256] = sl[tid + 256];
    }

    // ---- hidden = relu(c + b1), split back into A ----
    {
        int col0 = (lane & 3) * 2;
        int row_a = warp * 16 + (lane >> 2);
        int row_b = row_a + 8;
#pragma unroll
        for (int nt = 0; nt < 8; nt++) {
            int col = nt * 8 + col0;
            float bb0 = __ldg(&b1[col]), bb1 = __ldg(&b1[col + 1]);
            float h0 = fmaxf(c[nt][0] + bb0, 0.f);
            float h1 = fmaxf(c[nt][1] + bb1, 0.f);
            float h2 = fmaxf(c[nt][2] + bb0, 0.f);
            float h3 = fmaxf(c[nt][3] + bb1, 0.f);
            uint32_t ha = bf2_hi(h0, h1), hb = bf2_hi(h2, h3);
            uint32_t la = bf2_lo(h0, h1, ha), lb = bf2_lo(h2, h3, hb);
            uint32_t oa = sw128((uint32_t)(row_a * 128 + col * 2));
            uint32_t ob = sw128((uint32_t)(row_b * 128 + col * 2));
            *(uint32_t*)(sm.A_hi + oa) = ha;
            *(uint32_t*)(sm.A_lo + oa) = la;
            *(uint32_t*)(sm.A_hi + ob) = hb;
            *(uint32_t*)(sm.A_lo + ob) = lb;
        }
    }
    __syncthreads();

    // ---- stage 2 ----
    mma_stage(aHi, aLo, bHi, bLo, warp, lane, c);

    // ---- epilogue ----
    int col0 = (lane & 3) * 2;
    int row_a = warp * 16 + (lane >> 2);
    int row_b = row_a + 8;
    int node_a = node0 + row_a, node_b = node0 + row_b;

    if (!fcw) {
#pragma unroll
        for (int nt = 0; nt < 8; nt++) {
            int col = nt * 8 + col0;
            float bb0 = __ldg(&b2[col]), bb1 = __ldg(&b2[col + 1]);
            float2 oa = make_float2(c[nt][0] + bb0, c[nt][1] + bb1);
            float2 ob = make_float2(c[nt][2] + bb0, c[nt][3] + bb1);
            if (relu_out) {
                oa.x = fmaxf(oa.x, 0.f); oa.y = fmaxf(oa.y, 0.f);
                ob.x = fmaxf(ob.x, 0.f); ob.y = fmaxf(ob.y, 0.f);
            }
            if (node_a < NN) *(float2*)&hout[node_a * 64 + col] = oa;
            if (node_b < NN) *(float2*)&hout[node_b * 64 + col] = ob;
        }
    } else {
        float pa = 0.f, pb = 0.f;
#pragma unroll
        for (int nt = 0; nt < 8; nt++) {
            int col = nt * 8 + col0;
            float bb0 = __ldg(&b2[col]), bb1 = __ldg(&b2[col + 1]);
            float f0 = __ldg(&fcw[col]), f1 = __ldg(&fcw[col + 1]);
            pa += (c[nt][0] + bb0) * f0 + (c[nt][1] + bb1) * f1;
            pb += (c[nt][2] + bb0) * f0 + (c[nt][3] + bb1) * f1;
        }
        // reduce over the 4 lanes sharing a row (lane>>2 equal, lane&3 varies)
        pa += __shfl_xor_sync(0xffffffffu, pa, 1);
        pa += __shfl_xor_sync(0xffffffffu, pa, 2);
        pb += __shfl_xor_sync(0xffffffffu, pb, 1);
        pb += __shfl_xor_sync(0xffffffffu, pb, 2);
        if ((lane & 3) == 0) {
            if (node_a < NN) {
                int g = g_is32 ? __ldg(&((const int*)batch)[node_a])
                               : (int)__ldg(&((const long long*)batch)[node_a]);
                atomicAdd(&out[g], pa);
            }
            if (node_b < NN) {
                int g = g_is32 ? __ldg(&((const int*)batch)[node_b])
                               : (int)__ldg(&((const long long*)batch)[node_b]);
                atomicAdd(&out[g], pb);
            }
        }
    }
}

// ---------------------------------------------------------------------------
__global__ void init_out_kernel(float* __restrict__ out, const float* __restrict__ fcb) {
    if (threadIdx.x < GG) out[threadIdx.x] = fcb[0];
}

// ---------------------------------------------------------------------------
extern "C" void kernel_launch(void* const* d_in, const int* in_sizes, int n_in,
                              void* d_out, int out_size)
{
    const float* x   = (const float*)d_in[0];
    const void*  ei  = d_in[1];
    const void*  bat = d_in[2];
    const float* w1[3], *b1[3], *w2[3], *b2[3];
    for (int l = 0; l < 3; l++) {
        w1[l] = (const float*)d_in[3 + 4 * l];
        b1[l] = (const float*)d_in[4 + 4 * l];
        w2[l] = (const float*)d_in[5 + 4 * l];
        b2[l] = (const float*)d_in[6 + 4 * l];
    }
    const float* fcw = (const float*)d_in[15];
    const float* fcb = (const float*)d_in[16];
    float* out = (float*)d_out;

    float *agg, *hA, *hB;
    cudaGetSymbolAddress((void**)&agg, g_agg);
    cudaGetSymbolAddress((void**)&hA,  g_hA);
    cudaGetSymbolAddress((void**)&hB,  g_hB);

    const int edge_blocks   = (EE + 255) / 256;
    const int node_blocks   = (NN + 255) / 256;
    const int gather_blocks = (NN * 16 + 255) / 256;
    const int mlp_blocks    = (NN + 127) / 128;       // 782

    // weight pre-conversion (independent of CSR chain, cheap)
    wconv_kernel<<<96, 256>>>(w1[0], w2[0], w1[1], w2[1], w1[2], w2[2]);

    // ---- CSR-by-destination build ----
    zero_detect_kernel<<<node_blocks, 256>>>((const unsigned long long*)ei);
    hist_kernel<<<edge_blocks, 256>>>(ei);
    scan1_kernel<<<NPART, 1024>>>();
    scan23_kernel<<<node_blocks, 256>>>();
    fill_kernel<<<edge_blocks, 256>>>(ei);

    init_out_kernel<<<1, 256>>>(out, fcb);

    // ---- layer 0 ----
    gather_kernel<<<gather_blocks, 256>>>((const ulonglong2*)x, (ulonglong2*)agg);
    mlp_mma_kernel<<<mlp_blocks, 256>>>(agg, 0, b1[0], b2[0], hA, 1,
                                        (const float*)0, (const void*)0, (float*)0);
    // ---- layer 1 ----
    gather_kernel<<<gather_blocks, 256>>>((const ulonglong2*)hA, (ulonglong2*)agg);
    mlp_mma_kernel<<<mlp_blocks, 256>>>(agg, 1, b1[1], b2[1], hB, 1,
                                        (const float*)0, (const void*)0, (float*)0);
    // ---- layer 2: MLP + fused global_add_pool + FC ----
    gather_kernel<<<gather_blocks, 256>>>((const ulonglong2*)hB, (ulonglong2*)agg);
    mlp_mma_kernel<<<mlp_blocks, 256>>>(agg, 2, b1[2], b2[2], (float*)0, 0,
                                        fcw, bat, out);
}